// round 8
// baseline (speedup 1.0000x reference)
#include <cuda_runtime.h>
#include <cuda_bf16.h>
#include <cstdint>

#define NPTS 16384
#define ODIM 128
#define KNN  16
#define NCAND 64
#define NBLK 128          // 16384 / 128

// ---------------- scratch (no allocation allowed) ----------------
__device__ float g_base[NPTS * ODIM];              // x @ (W1a - W1b) + b1
__device__ float g_Bv[NPTS * ODIM];                // x @ W1b
__device__ __align__(16) float g_sq[NPTS];         // |x|^2
__device__ int   g_idx[NPTS * KNN];                // final knn indices
__device__ int   g_cand[NPTS * NCAND];             // coarse candidates (unsorted)
__device__ __align__(16) unsigned g_Af[NBLK * 4096];  // A fragments (bf16 hi)
__device__ __align__(16) unsigned g_Bf[NBLK * 4096];  // B fragments (bf16 hi)

// =================================================================
// precompute: base, Bv, sq.  4 points per block, 128 threads (o=tid)
// =================================================================
__global__ void __launch_bounds__(128) precompute_kernel(
    const float* __restrict__ x, const float* __restrict__ W1,
    const float* __restrict__ b1)
{
    const int n0  = blockIdx.x * 4;
    const int tid = threadIdx.x;
    __shared__ float xs[4][64];

    #pragma unroll
    for (int r = 0; r < 2; r++) {
        int li = r * 128 + tid;
        xs[li >> 6][li & 63] = x[n0 * 64 + li];
    }
    __syncthreads();

    float a1[4] = {0.f, 0.f, 0.f, 0.f};
    float a2[4] = {0.f, 0.f, 0.f, 0.f};
    #pragma unroll 4
    for (int c = 0; c < 64; c++) {
        float wa = W1[c * 128 + tid];
        float wb = W1[(64 + c) * 128 + tid];
        float wd = wa - wb;
        #pragma unroll
        for (int nn = 0; nn < 4; nn++) {
            float xv = xs[nn][c];
            a1[nn] = fmaf(xv, wd, a1[nn]);
            a2[nn] = fmaf(xv, wb, a2[nn]);
        }
    }
    float bb = b1[tid];
    #pragma unroll
    for (int nn = 0; nn < 4; nn++) {
        g_base[(n0 + nn) * 128 + tid] = a1[nn] + bb;
        g_Bv[(n0 + nn) * 128 + tid]  = a2[nn];
    }

    int w = tid >> 5, lane = tid & 31;
    float v = xs[w][lane] * xs[w][lane] + xs[w][lane + 32] * xs[w][lane + 32];
    #pragma unroll
    for (int off = 16; off > 0; off >>= 1)
        v += __shfl_xor_sync(0xffffffffu, v, off);
    if (lane == 0) g_sq[n0 + w] = v;
}

// =================================================================
// fragpack: bf16(hi) of x into mma fragment order (per 128-pt block).
// A frag u32 idx: (ks*8+mt)*128 + la*4 + rA
// B frag u32 idx: (ks*16+nt)*64 + la*2 + r1
// =================================================================
__global__ void __launch_bounds__(256) fragpack_kernel(const float* __restrict__ x)
{
    __shared__ unsigned sA[4096];
    __shared__ unsigned sB[4096];

    const int blk = blockIdx.x;
    const int tid = threadIdx.x;
    const int rl  = tid >> 1;
    const int c0  = (tid & 1) * 32;

    float v[32];
    const float4* xr = (const float4*)(x + (blk * 128 + rl) * 64 + c0);
    #pragma unroll
    for (int i = 0; i < 8; i++) {
        float4 t = xr[i];
        v[i * 4 + 0] = t.x; v[i * 4 + 1] = t.y;
        v[i * 4 + 2] = t.z; v[i * 4 + 3] = t.w;
    }

    const int mt = rl >> 4, gid = rl & 7, r0 = (rl >> 3) & 1;
    const int nt = rl >> 3;
    const int l  = gid * 4;

    #pragma unroll
    for (int cc = 0; cc < 32; cc += 2) {
        int c = c0 + cc;
        __nv_bfloat16 h0 = __float2bfloat16(v[cc]);
        __nv_bfloat16 h1 = __float2bfloat16(v[cc + 1]);
        unsigned uhi = ((unsigned)__bfloat16_as_ushort(h1) << 16) | __bfloat16_as_ushort(h0);

        int ks = c >> 4, cb = (c >> 1) & 3, r1 = (c >> 3) & 1;
        int la = l + cb;
        int rA = r1 * 2 + r0;
        sA[(ks * 8 + mt) * 128 + la * 4 + rA] = uhi;
        sB[(ks * 16 + nt) * 64 + la * 2 + r1] = uhi;
    }
    __syncthreads();

    uint4* dA = (uint4*)(g_Af + blk * 4096);
    uint4* dB = (uint4*)(g_Bf + blk * 4096);
    const uint4* s4A = (const uint4*)sA;
    const uint4* s4B = (const uint4*)sB;
    #pragma unroll
    for (int i = 0; i < 4; i++) {
        dA[i * 256 + tid] = s4A[i * 256 + tid];
        dB[i * 256 + tid] = s4B[i * 256 + tid];
    }
}

// =================================================================
// dummy: aligns ncu capture (-s 5 -c 1) onto knn_kernel (6th launch)
// =================================================================
__global__ void dummy_kernel() {}

// =================================================================
// coarse kNN via bf16 mma.sync, register-direct top-k (no smem staging).
// CTA: 128 queries. 8 warps; warp = 16 rows x 128 cols.
// Each lane scans its accumulators; 4 lanes/row each keep exact top-16
// of their disjoint 32-column slice -> NCAND=64 superset per query.
// =================================================================
#define OFF_A   0               // 4096 u32
#define OFF_B   4096            // 2 x 4096 u32
#define OFF_SQ  12288           // 2 x 128 floats
#define SM_U32  12544
#define SM_BYTES (SM_U32 * 4)

#define TOPK_INS(kd, ki, valx, jjx) do {                                   \
    float _d = (valx); int _j = (jjx);                                     \
    if (_d < kd[15]) {                                                     \
        _Pragma("unroll")                                                  \
        for (int _m = 0; _m < 16; _m++) {                                  \
            if (_d < kd[_m]) {                                             \
                float _td = kd[_m]; kd[_m] = _d; _d = _td;                 \
                int   _tj = ki[_m]; ki[_m] = _j; _j = _tj;                 \
            }                                                              \
        }                                                                  \
    }                                                                      \
} while (0)

__device__ __forceinline__ void cp16(unsigned saddr, const void* g)
{
    asm volatile("cp.async.cg.shared.global [%0], [%1], 16;" :: "r"(saddr), "l"(g));
}

__global__ void __launch_bounds__(256, 1) knn_kernel()
{
    extern __shared__ __align__(16) unsigned sm[];

    const int tid  = threadIdx.x;
    const int lane = tid & 31;
    const int wid  = tid >> 5;
    const int g    = lane >> 2;        // row within warp-half
    const int c    = lane & 3;         // column-pair group
    const unsigned smbase = (unsigned)__cvta_generic_to_shared(sm);

    // ---- initial loads: A block + B tile 0 + sq 0 ----
    {
        const uint4* gA = (const uint4*)(g_Af + blockIdx.x * 4096);
        #pragma unroll
        for (int i = 0; i < 4; i++)
            cp16(smbase + (i * 256 + tid) * 16, gA + i * 256 + tid);
        const uint4* gB = (const uint4*)(g_Bf);
        #pragma unroll
        for (int i = 0; i < 4; i++)
            cp16(smbase + (OFF_B + i * 1024) * 4 + tid * 16, gB + i * 256 + tid);
        if (tid < 32)
            cp16(smbase + OFF_SQ * 4 + tid * 16, g_sq + tid * 4);
    }
    asm volatile("cp.async.commit_group;");

    float kd0[16], kd1[16]; int ki0[16], ki1[16];
    #pragma unroll
    for (int m = 0; m < 16; m++) {
        kd0[m] = 1e30f; ki0[m] = 0;
        kd1[m] = 1e30f; ki1[m] = 0;
    }

    for (int jt = 0; jt < NBLK; jt++) {
        const int cur = jt & 1;
        // ---- prefetch next B tile (overlaps MMA + scan) ----
        if (jt + 1 < NBLK) {
            const uint4* gB = (const uint4*)(g_Bf + (jt + 1) * 4096);
            #pragma unroll
            for (int i = 0; i < 4; i++)
                cp16(smbase + (OFF_B + ((jt + 1) & 1) * 4096 + i * 1024) * 4 + tid * 16,
                     gB + i * 256 + tid);
            if (tid < 32)
                cp16(smbase + (OFF_SQ + ((jt + 1) & 1) * 128) * 4 + tid * 16,
                     g_sq + (jt + 1) * 128 + tid * 4);
        }
        asm volatile("cp.async.commit_group;");
        asm volatile("cp.async.wait_group 1;");
        __syncthreads();

        // ---- A fragments for this warp's 16 rows (ni-invariant) ----
        unsigned a[4][4];
        #pragma unroll
        for (int ks = 0; ks < 4; ks++) {
            uint4 t = *(const uint4*)(sm + (ks * 8 + wid) * 128 + lane * 4);
            a[ks][0] = t.x; a[ks][1] = t.y; a[ks][2] = t.z; a[ks][3] = t.w;
        }
        const float* sqb = (const float*)(sm + OFF_SQ + cur * 128);
        const unsigned* Bb = sm + OFF_B + cur * 4096;

        #pragma unroll
        for (int ni = 0; ni < 16; ni++) {
            unsigned b[4][2];
            #pragma unroll
            for (int ks = 0; ks < 4; ks++) {
                uint2 t = *(const uint2*)(Bb + (ks * 16 + ni) * 64 + lane * 2);
                b[ks][0] = t.x; b[ks][1] = t.y;
            }
            float acc[4] = {0.f, 0.f, 0.f, 0.f};
            #pragma unroll
            for (int ks = 0; ks < 4; ks++)
                asm volatile(
                    "mma.sync.aligned.m16n8k16.row.col.f32.bf16.bf16.f32 "
                    "{%0,%1,%2,%3}, {%4,%5,%6,%7}, {%8,%9}, {%0,%1,%2,%3};"
                    : "+f"(acc[0]), "+f"(acc[1]), "+f"(acc[2]), "+f"(acc[3])
                    : "r"(a[ks][0]), "r"(a[ks][1]), "r"(a[ks][2]), "r"(a[ks][3]),
                      "r"(b[ks][0]), "r"(b[ks][1]));

            // scores for cols (ni*8 + c*2, +1), rows g and g+8
            float2 q = *(const float2*)&sqb[ni * 8 + c * 2];
            float d0 = fmaf(0.5f, q.x, -acc[0]);
            float d1 = fmaf(0.5f, q.y, -acc[1]);
            float d2 = fmaf(0.5f, q.x, -acc[2]);
            float d3 = fmaf(0.5f, q.y, -acc[3]);
            int jb = jt * 128 + ni * 8 + c * 2;
            TOPK_INS(kd0, ki0, d0, jb);
            TOPK_INS(kd0, ki0, d1, jb + 1);
            TOPK_INS(kd1, ki1, d2, jb);
            TOPK_INS(kd1, ki1, d3, jb + 1);
        }
        __syncthreads();
    }

    // ---- dump candidates (order irrelevant; refine re-scores exactly) ----
    {
        const int row0 = blockIdx.x * 128 + wid * 16 + g;
        int* cd0 = g_cand + row0 * NCAND + c * 16;
        int* cd1 = g_cand + (row0 + 8) * NCAND + c * 16;
        #pragma unroll
        for (int m = 0; m < 16; m++) {
            cd0[m] = ki0[m];
            cd1[m] = ki1[m];
        }
    }
}

// =================================================================
// refine: exact fp32 re-score of 64 candidates, select true top-16.
// 4 queries per block, 64 threads per query (smem ranking).
// =================================================================
__global__ void __launch_bounds__(256) refine_kernel(const float* __restrict__ x)
{
    __shared__ float xi[4][64];
    __shared__ float ss[4][64];
    const int tid = threadIdx.x;
    const int ql  = tid >> 6;          // local query 0..3
    const int i   = tid & 63;          // candidate slot
    const int q0  = blockIdx.x * 4;

    xi[ql][i] = x[q0 * 64 + tid];      // 256 floats = 4 queries x 64 dims
    __syncthreads();

    const int q  = q0 + ql;
    const int cj = g_cand[q * NCAND + i];
    const float4* xr = (const float4*)(x + cj * 64);
    float dot = 0.f;
    #pragma unroll
    for (int u = 0; u < 16; u++) {
        float4 v = xr[u];
        dot = fmaf(xi[ql][u * 4 + 0], v.x, dot);
        dot = fmaf(xi[ql][u * 4 + 1], v.y, dot);
        dot = fmaf(xi[ql][u * 4 + 2], v.z, dot);
        dot = fmaf(xi[ql][u * 4 + 3], v.w, dot);
    }
    float s = fmaf(0.5f, g_sq[cj], -dot);
    ss[ql][i] = s;
    __syncthreads();

    int rank = 0;
    #pragma unroll 8
    for (int m = 0; m < NCAND; m++) {
        float sv = ss[ql][m];
        rank += (sv < s) || (sv == s && m < i);
    }
    if (rank < KNN)
        g_idx[q * KNN + rank] = cj;
}

// =================================================================
// aggregate: s = mean_k relu(base + Bv[j_k]);  out = s @ W2 + b2
// 8 points per block, 128 threads (o = tid), W2 read coalesced.
// =================================================================
__global__ void __launch_bounds__(128) aggregate_kernel(
    const float* __restrict__ W2, const float* __restrict__ b2,
    float* __restrict__ out)
{
    const int n0  = blockIdx.x * 8;
    const int tid = threadIdx.x;
    __shared__ float ss[8][128];
    __shared__ int sidx[128];

    sidx[tid] = g_idx[n0 * 16 + tid];
    __syncthreads();

    #pragma unroll
    for (int p = 0; p < 8; p++) {
        float bv  = g_base[(n0 + p) * 128 + tid];
        float acc = 0.f;
        #pragma unroll
        for (int k = 0; k < 16; k++) {
            float v = bv + g_Bv[sidx[p * 16 + k] * 128 + tid];
            acc += fmaxf(v, 0.f);
        }
        ss[p][tid] = acc * (1.0f / 16.0f);
    }
    __syncthreads();

    float r[8];
    float bb = b2[tid];
    #pragma unroll
    for (int p = 0; p < 8; p++) r[p] = bb;

    #pragma unroll 4
    for (int i = 0; i < 128; i++) {
        float w = W2[i * 128 + tid];
        #pragma unroll
        for (int p = 0; p < 8; p++)
            r[p] = fmaf(ss[p][i], w, r[p]);
    }
    #pragma unroll
    for (int p = 0; p < 8; p++)
        out[(n0 + p) * 128 + tid] = r[p];
}

// =================================================================
extern "C" void kernel_launch(void* const* d_in, const int* in_sizes, int n_in,
                              void* d_out, int out_size)
{
    const float* x  = (const float*)d_in[0];
    const float* W1 = (const float*)d_in[1];
    const float* b1 = (const float*)d_in[2];
    const float* W2 = (const float*)d_in[3];
    const float* b2 = (const float*)d_in[4];
    float* out = (float*)d_out;

    cudaFuncSetAttribute(knn_kernel,
                         cudaFuncAttributeMaxDynamicSharedMemorySize, SM_BYTES);

    precompute_kernel<<<NPTS / 4, 128>>>(x, W1, b1);       // launch 1
    fragpack_kernel<<<NBLK, 256>>>(x);                     // launch 2
    dummy_kernel<<<1, 32>>>();                             // launch 3
    dummy_kernel<<<1, 32>>>();                             // launch 4
    dummy_kernel<<<1, 32>>>();                             // launch 5
    knn_kernel<<<NBLK, 256, SM_BYTES>>>();                 // launch 6 (ncu -s 5 -c 1)
    refine_kernel<<<NPTS / 4, 256>>>(x);                   // launch 7
    aggregate_kernel<<<NPTS / 8, 128>>>(W2, b2, out);      // launch 8
}